// round 1
// baseline (speedup 1.0000x reference)
#include <cuda_runtime.h>
#include <cuda_bf16.h>
#include <math.h>

#define L_TOT 5456
#define NB    32
#define FIN   32
#define FOUT  64
#define BATCH 4
#define NGRID 12
#define ZI    128   // BATCH*FIN
#define ZO    256   // BATCH*FOUT

// -------- scratch (device globals; no runtime allocation) --------
__device__ float2 g_Xf[(size_t)BATCH * FIN * NB * NB * NB];        // 4.19M  (33.5 MB)
__device__ float2 g_xh[(size_t)L_TOT * ZI];                        // 698K   (5.6 MB)
__device__ float2 g_yh[(size_t)L_TOT * FIN * FOUT];                // 11.17M (89 MB)
__device__ float2 g_zh[(size_t)ZO * L_TOT];                        // 1.40M  (11.2 MB), layout [zo][lmn]

__device__ __forceinline__ int baseL(int l) {
    // sum_{l'<l} (2l'+1)^2 = l(2l-1)(2l+1)/3
    return l * (2 * l - 1) * (2 * l + 1) / 3;
}

// ---------------- K1: forward FFT2 of x (per 32x32 plane) ----------------
__global__ void k_fft_fwd(const float* __restrict__ x) {
    __shared__ float  xs[32][33];
    __shared__ float2 T[32][33];
    __shared__ float2 W[32];
    int plane = blockIdx.x;
    int tid = threadIdx.x;
    int r = tid >> 5, c = tid & 31;
    if (tid < 32) {
        float s, co;
        sincosf(-6.283185307179586f * (float)tid / 32.0f, &s, &co);
        W[tid] = make_float2(co, s);
    }
    xs[r][c] = x[(size_t)plane * 1024 + tid];
    __syncthreads();
    // stage 1 (over a): T[ma=r][g=c] = sum_a xs[a][c] * W[(r*a)&31]
    float2 acc = make_float2(0.f, 0.f);
    #pragma unroll
    for (int a = 0; a < 32; a++) {
        float v = xs[a][c];
        float2 w = W[(r * a) & 31];
        acc.x += v * w.x; acc.y += v * w.y;
    }
    T[r][c] = acc;
    __syncthreads();
    // stage 2 (over g): Xf[ma=r][ng=c] = sum_g T[r][g] * W[(c*g)&31]
    float2 o2 = make_float2(0.f, 0.f);
    #pragma unroll
    for (int g = 0; g < 32; g++) {
        float2 t = T[r][g];
        float2 w = W[(c * g) & 31];
        o2.x += t.x * w.x - t.y * w.y;
        o2.y += t.x * w.y + t.y * w.x;
    }
    g_Xf[(size_t)plane * 1024 + tid] = o2;
}

// ---------------- K2: xh[lmn][zi] = sum_b wf[b,lmn] * Xf[z,i,b,m&31,n&31] ----------------
__global__ void k_fwd_contract(const float* __restrict__ wf) {
    int lmn = blockIdx.x;
    int l = 0;
    while (l < 15 && lmn >= baseL(l + 1)) ++l;
    int n1 = 2 * l + 1;
    int rem = lmn - baseL(l);
    int m = rem / n1 - l, n = rem % n1 - l;
    int mi = m & 31, ni = n & 31;
    int t = threadIdx.x;  // z*32+i
    const float2* xp = g_Xf + (size_t)t * (NB * 1024) + mi * 32 + ni;
    float2 acc = make_float2(0.f, 0.f);
    #pragma unroll
    for (int b = 0; b < 32; b++) {
        float w = __ldg(&wf[b * L_TOT + lmn]);
        float2 v = xp[(size_t)b * 1024];
        acc.x += w * v.x; acc.y += w * v.y;
    }
    g_xh[(size_t)lmn * ZI + t] = acc;
}

// ---------------- K3: yh[lmn][i][o] = sum_j D[lmn,j] * kernel[i,o,j] ----------------
__global__ void k_kernel_ft(const float* __restrict__ D_re, const float* __restrict__ D_im,
                            const float* __restrict__ kern) {
    int lmn = blockIdx.x;
    __shared__ float2 sD[NGRID];
    int tid = threadIdx.x;
    if (tid < NGRID) sD[tid] = make_float2(D_re[lmn * NGRID + tid], D_im[lmn * NGRID + tid]);
    __syncthreads();
    int q = blockIdx.y * 1024 + tid;  // q = i*64 + o
    const float* kp = kern + (size_t)q * NGRID;
    float2 acc = make_float2(0.f, 0.f);
    #pragma unroll
    for (int j = 0; j < NGRID; j++) {
        float kv = __ldg(&kp[j]);
        acc.x += kv * sD[j].x; acc.y += kv * sD[j].y;
    }
    g_yh[(size_t)lmn * 2048 + q] = acc;
}

// ---------------- K4: per-l block matmul  zh = x^l @ y^l ----------------
// block = (l, m, n'-chunk of 8), descending l. threads 256 = (z,o).
__global__ __launch_bounds__(256) void k_so3mm() {
    int b = blockIdx.x;
    int l = 0, m = 0, ch = 0;
    {
        int off = 0;
        for (int ll = 15; ll >= 0; --ll) {
            int n1 = 2 * ll + 1, nch = (n1 + 7) >> 3;
            int cnt = n1 * nch;
            if (b < off + cnt) { l = ll; int r = b - off; m = r / nch; ch = r % nch; break; }
            off += cnt;
        }
    }
    int n1 = 2 * l + 1;
    int base = baseL(l);
    __shared__ float2 sx[31 * ZI];
    int tid = threadIdx.x;
    // xh rows for (l, m, k=0..n1-1) are contiguous
    const float2* xsrc = g_xh + (size_t)(base + m * n1) * ZI;
    for (int idx = tid; idx < n1 * ZI; idx += 256) sx[idx] = xsrc[idx];
    __syncthreads();

    int o = tid & 63, z = tid >> 6;
    int np0 = ch * 8;
    int np1 = np0 + 8 < n1 ? np0 + 8 : n1;
    for (int np = np0; np < np1; np += 2) {
        bool two = (np + 1 < np1);
        float2 acc0 = make_float2(0.f, 0.f), acc1 = make_float2(0.f, 0.f);
        for (int k = 0; k < n1; k++) {
            const float2* ya = g_yh + ((size_t)(base + k * n1 + np)) * 2048 + o;
            const float2* yb = ya + 2048;
            const float2* xk = sx + k * ZI + z * FIN;
            #pragma unroll 8
            for (int i = 0; i < FIN; i++) {
                float2 a  = xk[i];
                float2 b0 = ya[(size_t)i * 64];
                acc0.x += a.x * b0.x - a.y * b0.y;
                acc0.y += a.x * b0.y + a.y * b0.x;
                if (two) {
                    float2 b1 = yb[(size_t)i * 64];
                    acc1.x += a.x * b1.x - a.y * b1.y;
                    acc1.y += a.x * b1.y + a.y * b1.x;
                }
            }
        }
        size_t zrow = (size_t)(z * 64 + o) * L_TOT;
        g_zh[zrow + base + m * n1 + np] = acc0;
        if (two) g_zh[zrow + base + m * n1 + np + 1] = acc1;
    }
}

// ---------------- K5: fused scatter (wigner_inv * zh -> bins) + inverse FFT2 + real + bias ----------------
__global__ __launch_bounds__(1024) void k_inv(const float* __restrict__ wig,
                                              const float* __restrict__ bias,
                                              float* __restrict__ out) {
    __shared__ float  wrow[L_TOT];
    __shared__ float2 plane[32][33];
    __shared__ float2 U[32][33];
    __shared__ float2 W[32];
    int blk = blockIdx.x;           // z*2048 + o*32 + b
    int bb = blk & 31;
    int o  = (blk >> 5) & 63;
    int z  = blk >> 11;
    int tid = threadIdx.x;
    int r = tid >> 5, c = tid & 31;
    if (tid < 32) {
        float s, co;
        sincosf(6.283185307179586f * (float)tid / 32.0f, &s, &co);  // inverse: e^{+i...}
        W[tid] = make_float2(co, s);
    }
    plane[r][c] = make_float2(0.f, 0.f);
    for (int q = tid; q < L_TOT; q += 1024) wrow[q] = wig[bb * L_TOT + q];
    __syncthreads();
    // bin accumulation: one thread per (m,n) in [-15,15]^2
    if (tid < 961) {
        int m = tid / 31 - 15, n = tid % 31 - 15;
        int am = m < 0 ? -m : m, an = n < 0 ? -n : n;
        int lmin = am > an ? am : an;
        float2 acc = make_float2(0.f, 0.f);
        const float2* zrow = g_zh + (size_t)(z * 64 + o) * L_TOT;
        for (int l = lmin; l < 16; ++l) {
            int idx = baseL(l) + (m + l) * (2 * l + 1) + (n + l);
            float w = wrow[idx];
            float2 v = zrow[idx];
            acc.x += w * v.x; acc.y += w * v.y;
        }
        plane[m & 31][n & 31] = acc;
    }
    __syncthreads();
    // stage A (over mm): U[a=r][nn=c] = sum_mm plane[mm][c] * W[(mm*r)&31]
    float2 u = make_float2(0.f, 0.f);
    #pragma unroll
    for (int mm = 0; mm < 32; mm++) {
        float2 p = plane[mm][c];
        float2 w = W[(mm * r) & 31];
        u.x += p.x * w.x - p.y * w.y;
        u.y += p.x * w.y + p.y * w.x;
    }
    U[r][c] = u;
    __syncthreads();
    // stage B (over nn), real part only: out[a=r][g=c]
    float acc = 0.f;
    #pragma unroll
    for (int nn = 0; nn < 32; nn++) {
        float2 t = U[r][nn];
        float2 w = W[(nn * c) & 31];
        acc += t.x * w.x - t.y * w.y;
    }
    out[(size_t)blk * 1024 + tid] = acc * (1.0f / 1024.0f) + __ldg(&bias[o]);
}

// ---------------- launch ----------------
extern "C" void kernel_launch(void* const* d_in, const int* in_sizes, int n_in,
                              void* d_out, int out_size) {
    const float* x    = (const float*)d_in[0];
    const float* kern = (const float*)d_in[1];
    const float* bias = (const float*)d_in[2];
    const float* wf   = (const float*)d_in[3];
    const float* wi   = (const float*)d_in[4];
    const float* D_re = (const float*)d_in[5];
    const float* D_im = (const float*)d_in[6];
    float* out = (float*)d_out;

    k_fft_fwd<<<BATCH * FIN * NB, 1024>>>(x);
    k_fwd_contract<<<L_TOT, ZI>>>(wf);
    k_kernel_ft<<<dim3(L_TOT, 2), 1024>>>(D_re, D_im, kern);
    k_so3mm<<<800, 256>>>();
    k_inv<<<BATCH * FOUT * NB, 1024>>>(wi, bias, out);
}

// round 2
// speedup vs baseline: 1.5063x; 1.5063x over previous
#include <cuda_runtime.h>
#include <cuda_bf16.h>
#include <math.h>

#define L_TOT 5456
#define NB    32
#define FIN   32
#define FOUT  64
#define BATCH 4
#define NGRID 12
#define ZI    128   // BATCH*FIN
#define ZO    256   // BATCH*FOUT

// -------- scratch (device globals; no runtime allocation) --------
// Xf layout: [b*1024 + mi*32 + ni][zi]  (zi innermost -> coalesced in K2)
__device__ float2 g_Xf[(size_t)NB * 1024 * ZI];                    // 33.5 MB
__device__ float2 g_xh[(size_t)L_TOT * ZI];                        // 5.6 MB
__device__ float2 g_yh[(size_t)L_TOT * FIN * FOUT];                // 89 MB (L2-resident)
__device__ float2 g_zh[(size_t)ZO * L_TOT];                        // 11.2 MB, layout [zo][lmn]

__device__ __forceinline__ int baseL(int l) {
    // sum_{l'<l} (2l'+1)^2 = l(2l-1)(2l+1)/3
    return l * (2 * l - 1) * (2 * l + 1) / 3;
}

// ---------------- K1: forward FFT2 of x, writes transposed Xf ----------------
__global__ __launch_bounds__(1024) void k_fft_fwd(const float* __restrict__ x) {
    __shared__ float  xs[32][33];
    __shared__ float2 T[32][33];
    __shared__ float2 W[32];
    int plane = blockIdx.x;                 // = zi*32 + b
    int zi = plane >> 5, b = plane & 31;
    int tid = threadIdx.x;
    int r = tid >> 5, c = tid & 31;
    if (tid < 32) {
        float s, co;
        sincosf(-6.283185307179586f * (float)tid / 32.0f, &s, &co);
        W[tid] = make_float2(co, s);
    }
    xs[r][c] = x[(size_t)plane * 1024 + tid];
    __syncthreads();
    // stage 1 (over a): T[ma=r][g=c] = sum_a xs[a][c] * W[(r*a)&31]
    float2 acc = make_float2(0.f, 0.f);
    #pragma unroll
    for (int a = 0; a < 32; a++) {
        float v = xs[a][c];
        float2 w = W[(r * a) & 31];
        acc.x += v * w.x; acc.y += v * w.y;
    }
    T[r][c] = acc;
    __syncthreads();
    // stage 2 (over g): Xf[ma=r][ng=c] = sum_g T[r][g] * W[(c*g)&31]
    float2 o2 = make_float2(0.f, 0.f);
    #pragma unroll
    for (int g = 0; g < 32; g++) {
        float2 t = T[r][g];
        float2 w = W[(c * g) & 31];
        o2.x += t.x * w.x - t.y * w.y;
        o2.y += t.x * w.y + t.y * w.x;
    }
    g_Xf[((size_t)(b * 1024 + tid)) * ZI + zi] = o2;
}

// ---------------- K2: xh[lmn][zi] = sum_b wf[b,lmn] * Xf[b,m&31,n&31][zi] ----------------
__global__ __launch_bounds__(128) void k_fwd_contract(const float* __restrict__ wf) {
    int lmn = blockIdx.x;
    int l = 0;
    while (l < 15 && lmn >= baseL(l + 1)) ++l;
    int n1 = 2 * l + 1;
    int rem = lmn - baseL(l);
    int m = rem / n1 - l, n = rem % n1 - l;
    int mi = m & 31, ni = n & 31;
    __shared__ float sw[32];
    int t = threadIdx.x;  // zi
    if (t < 32) sw[t] = __ldg(&wf[t * L_TOT + lmn]);
    __syncthreads();
    const float2* xp = g_Xf + ((size_t)(mi * 32 + ni)) * ZI + t;
    float2 acc = make_float2(0.f, 0.f);
    #pragma unroll 8
    for (int b = 0; b < 32; b++) {
        float w = sw[b];
        float2 v = xp[(size_t)b * 1024 * ZI];
        acc.x += w * v.x; acc.y += w * v.y;
    }
    g_xh[(size_t)lmn * ZI + t] = acc;
}

// ---------------- K3: yh[lmn][i][o] = sum_j D[lmn,j] * kernel[i,o,j] ----------------
__global__ __launch_bounds__(1024) void k_kernel_ft(const float* __restrict__ D_re,
                                                    const float* __restrict__ D_im,
                                                    const float* __restrict__ kern) {
    int lmn = blockIdx.x;
    __shared__ float2 sD[NGRID];
    int tid = threadIdx.x;
    if (tid < NGRID) sD[tid] = make_float2(D_re[lmn * NGRID + tid], D_im[lmn * NGRID + tid]);
    __syncthreads();
    int q = blockIdx.y * 1024 + tid;  // q = i*64 + o
    const float* kp = kern + (size_t)q * NGRID;
    float2 acc = make_float2(0.f, 0.f);
    #pragma unroll
    for (int j = 0; j < NGRID; j++) {
        float kv = __ldg(&kp[j]);
        acc.x += kv * sD[j].x; acc.y += kv * sD[j].y;
    }
    g_yh[(size_t)lmn * 2048 + q] = acc;
}

// ---------------- K4: per-l block matmul  zh = x^l @ y^l ----------------
// block = (l desc, m, chunk of 4 np). 256 threads = z(4) x npq(2) x opair(32).
// Each thread: 2 np x 2 o complex accumulators; y loaded as float4 (LDG.128).
#define K4_GRID 1488
__global__ __launch_bounds__(256) void k_so3mm() {
    int b = blockIdx.x;
    int l = 0, m = 0, ch = 0;
    {
        int off = 0;
        for (int ll = 15; ll >= 0; --ll) {
            int n1 = 2 * ll + 1, nch = (n1 + 3) >> 2;
            int cnt = n1 * nch;
            if (b < off + cnt) { l = ll; int r = b - off; m = r / nch; ch = r % nch; break; }
            off += cnt;
        }
    }
    int n1 = 2 * l + 1;
    int base = baseL(l);
    __shared__ float2 sx[31 * ZI];
    int tid = threadIdx.x;
    const float2* xsrc = g_xh + (size_t)(base + m * n1) * ZI;
    for (int idx = tid; idx < n1 * ZI; idx += 256) sx[idx] = xsrc[idx];
    __syncthreads();

    int op  = tid & 31;          // o pair: o = 2*op, 2*op+1
    int npq = (tid >> 5) & 1;    // which np-pair within the chunk of 4
    int z   = tid >> 6;          // 0..3
    int npa = ch * 4 + npq * 2;
    int npb = npa + 1;
    bool va = npa < n1, vb = npb < n1;
    int npa_c = va ? npa : n1 - 1;
    int npb_c = vb ? npb : n1 - 1;

    float2 a00 = make_float2(0.f, 0.f);  // np_a, o0
    float2 a01 = make_float2(0.f, 0.f);  // np_a, o1
    float2 a10 = make_float2(0.f, 0.f);  // np_b, o0
    float2 a11 = make_float2(0.f, 0.f);  // np_b, o1

    for (int k = 0; k < n1; k++) {
        const float4* pa = reinterpret_cast<const float4*>(
            g_yh + ((size_t)(base + k * n1 + npa_c)) * 2048);
        const float4* pb = reinterpret_cast<const float4*>(
            g_yh + ((size_t)(base + k * n1 + npb_c)) * 2048);
        const float2* xr = sx + k * ZI + z * FIN;
        #pragma unroll 8
        for (int i = 0; i < FIN; i++) {
            float2 a  = xr[i];
            float4 y0 = __ldg(&pa[i * 32 + op]);
            float4 y1 = __ldg(&pb[i * 32 + op]);
            a00.x += a.x * y0.x - a.y * y0.y;
            a00.y += a.x * y0.y + a.y * y0.x;
            a01.x += a.x * y0.z - a.y * y0.w;
            a01.y += a.x * y0.w + a.y * y0.z;
            a10.x += a.x * y1.x - a.y * y1.y;
            a10.y += a.x * y1.y + a.y * y1.x;
            a11.x += a.x * y1.z - a.y * y1.w;
            a11.y += a.x * y1.w + a.y * y1.z;
        }
    }
    int o0 = 2 * op, o1 = o0 + 1;
    size_t row0 = (size_t)(z * 64 + o0) * L_TOT;
    size_t row1 = (size_t)(z * 64 + o1) * L_TOT;
    int idxa = base + m * n1 + npa;
    int idxb = base + m * n1 + npb;
    if (va) { g_zh[row0 + idxa] = a00; g_zh[row1 + idxa] = a01; }
    if (vb) { g_zh[row0 + idxb] = a10; g_zh[row1 + idxb] = a11; }
}

// ---------------- K5: fused scatter (wigner_inv * zh -> bins) + inverse FFT2 + real + bias ----------------
__global__ __launch_bounds__(1024) void k_inv(const float* __restrict__ wig,
                                              const float* __restrict__ bias,
                                              float* __restrict__ out) {
    __shared__ float2 plane[32][33];
    __shared__ float2 U[32][33];
    __shared__ float2 W[32];
    int blk = blockIdx.x;           // z*2048 + o*32 + b
    int bb = blk & 31;
    int o  = (blk >> 5) & 63;
    int z  = blk >> 11;
    int tid = threadIdx.x;
    int r = tid >> 5, c = tid & 31;
    if (tid < 32) {
        float s, co;
        sincosf(6.283185307179586f * (float)tid / 32.0f, &s, &co);  // inverse: e^{+i...}
        W[tid] = make_float2(co, s);
    }
    plane[r][c] = make_float2(0.f, 0.f);
    __syncthreads();
    // bin accumulation: one thread per (m,n) in [-15,15]^2
    if (tid < 961) {
        int m = tid / 31 - 15, n = tid % 31 - 15;
        int am = m < 0 ? -m : m, an = n < 0 ? -n : n;
        int lmin = am > an ? am : an;
        float2 acc = make_float2(0.f, 0.f);
        const float2* zrow = g_zh + (size_t)(z * 64 + o) * L_TOT;
        const float*  wp   = wig + (size_t)bb * L_TOT;
        for (int l = lmin; l < 16; ++l) {
            int idx = baseL(l) + (m + l) * (2 * l + 1) + (n + l);
            float w = __ldg(&wp[idx]);
            float2 v = zrow[idx];
            acc.x += w * v.x; acc.y += w * v.y;
        }
        plane[m & 31][n & 31] = acc;
    }
    __syncthreads();
    // stage A (over mm): U[a=r][nn=c] = sum_mm plane[mm][c] * W[(mm*r)&31]
    float2 u = make_float2(0.f, 0.f);
    #pragma unroll
    for (int mm = 0; mm < 32; mm++) {
        float2 p = plane[mm][c];
        float2 w = W[(mm * r) & 31];
        u.x += p.x * w.x - p.y * w.y;
        u.y += p.x * w.y + p.y * w.x;
    }
    U[r][c] = u;
    __syncthreads();
    // stage B (over nn), real part only: out[a=r][g=c]
    float acc = 0.f;
    #pragma unroll
    for (int nn = 0; nn < 32; nn++) {
        float2 t = U[r][nn];
        float2 w = W[(nn * c) & 31];
        acc += t.x * w.x - t.y * w.y;
    }
    out[(size_t)blk * 1024 + tid] = acc * (1.0f / 1024.0f) + __ldg(&bias[o]);
}

// ---------------- launch ----------------
extern "C" void kernel_launch(void* const* d_in, const int* in_sizes, int n_in,
                              void* d_out, int out_size) {
    const float* x    = (const float*)d_in[0];
    const float* kern = (const float*)d_in[1];
    const float* bias = (const float*)d_in[2];
    const float* wf   = (const float*)d_in[3];
    const float* wi   = (const float*)d_in[4];
    const float* D_re = (const float*)d_in[5];
    const float* D_im = (const float*)d_in[6];
    float* out = (float*)d_out;

    k_fft_fwd<<<BATCH * FIN * NB, 1024>>>(x);
    k_fwd_contract<<<L_TOT, ZI>>>(wf);
    k_kernel_ft<<<dim3(L_TOT, 2), 1024>>>(D_re, D_im, kern);
    k_so3mm<<<K4_GRID, 256>>>();
    k_inv<<<BATCH * FOUT * NB, 1024>>>(wi, bias, out);
}

// round 4
// speedup vs baseline: 1.7486x; 1.1609x over previous
#include <cuda_runtime.h>
#include <cuda_bf16.h>
#include <math.h>

#define L_TOT 5456
#define NB    32
#define FIN   32
#define FOUT  64
#define BATCH 4
#define NGRID 12
#define ZI    128   // BATCH*FIN
#define ZO    256   // BATCH*FOUT

// -------- scratch (device globals; no runtime allocation) --------
// Xf layout: [b*1024 + mi*32 + ni][zi]  (zi innermost -> coalesced in K2)
__device__ float2 g_Xf[(size_t)NB * 1024 * ZI];                    // 33.5 MB
__device__ float2 g_xh[(size_t)L_TOT * ZI];                        // 5.6 MB
__device__ float2 g_yh[(size_t)L_TOT * FIN * FOUT];                // 89 MB (L2-resident)
__device__ float2 g_zh[(size_t)ZO * L_TOT];                        // 11.2 MB, layout [zo][lmn]

__device__ __forceinline__ int baseL(int l) {
    // sum_{l'<l} (2l'+1)^2 = l(2l-1)(2l+1)/3
    return l * (2 * l - 1) * (2 * l + 1) / 3;
}

// ---------------- K1: forward FFT2 of x, writes transposed Xf ----------------
__global__ __launch_bounds__(1024) void k_fft_fwd(const float* __restrict__ x) {
    __shared__ float  xs[32][33];
    __shared__ float2 T[32][33];
    __shared__ float2 W[32];
    int plane = blockIdx.x;                 // = zi*32 + b
    int zi = plane >> 5, b = plane & 31;
    int tid = threadIdx.x;
    int r = tid >> 5, c = tid & 31;
    if (tid < 32) {
        float s, co;
        sincosf(-6.283185307179586f * (float)tid / 32.0f, &s, &co);
        W[tid] = make_float2(co, s);
    }
    xs[r][c] = x[(size_t)plane * 1024 + tid];
    __syncthreads();
    float2 acc = make_float2(0.f, 0.f);
    #pragma unroll
    for (int a = 0; a < 32; a++) {
        float v = xs[a][c];
        float2 w = W[(r * a) & 31];
        acc.x += v * w.x; acc.y += v * w.y;
    }
    T[r][c] = acc;
    __syncthreads();
    float2 o2 = make_float2(0.f, 0.f);
    #pragma unroll
    for (int g = 0; g < 32; g++) {
        float2 t = T[r][g];
        float2 w = W[(c * g) & 31];
        o2.x += t.x * w.x - t.y * w.y;
        o2.y += t.x * w.y + t.y * w.x;
    }
    g_Xf[((size_t)(b * 1024 + tid)) * ZI + zi] = o2;
}

// ---------------- K2: xh[lmn][zi] = sum_b wf[b,lmn] * Xf[b,m&31,n&31][zi] ----------------
__global__ __launch_bounds__(128) void k_fwd_contract(const float* __restrict__ wf) {
    int lmn = blockIdx.x;
    int l = 0;
    while (l < 15 && lmn >= baseL(l + 1)) ++l;
    int n1 = 2 * l + 1;
    int rem = lmn - baseL(l);
    int m = rem / n1 - l, n = rem % n1 - l;
    int mi = m & 31, ni = n & 31;
    __shared__ float sw[32];
    int t = threadIdx.x;  // zi
    if (t < 32) sw[t] = __ldg(&wf[t * L_TOT + lmn]);
    __syncthreads();
    const float2* xp = g_Xf + ((size_t)(mi * 32 + ni)) * ZI + t;
    float2 acc = make_float2(0.f, 0.f);
    #pragma unroll 8
    for (int b = 0; b < 32; b++) {
        float w = sw[b];
        float2 v = xp[(size_t)b * 1024 * ZI];
        acc.x += w * v.x; acc.y += w * v.y;
    }
    g_xh[(size_t)lmn * ZI + t] = acc;
}

// ---------------- K3: yh[lmn][i][o] = sum_j D[lmn,j] * kernel[i,o,j] ----------------
__global__ __launch_bounds__(1024) void k_kernel_ft(const float* __restrict__ D_re,
                                                    const float* __restrict__ D_im,
                                                    const float* __restrict__ kern) {
    int lmn = blockIdx.x;
    __shared__ float2 sD[NGRID];
    int tid = threadIdx.x;
    if (tid < NGRID) sD[tid] = make_float2(D_re[lmn * NGRID + tid], D_im[lmn * NGRID + tid]);
    __syncthreads();
    int q = blockIdx.y * 1024 + tid;  // q = i*64 + o
    const float* kp = kern + (size_t)q * NGRID;
    float2 acc = make_float2(0.f, 0.f);
    #pragma unroll
    for (int j = 0; j < NGRID; j++) {
        float kv = __ldg(&kp[j]);
        acc.x += kv * sD[j].x; acc.y += kv * sD[j].y;
    }
    g_yh[(size_t)lmn * 2048 + q] = acc;
}

// ---------------- K4: per-l block matmul  zh = x^l @ y^l ----------------
// block = (l desc, m, chunk of 8 np). 256 threads = npp(8) x op(32).
// Each thread: 1 np, o-pair (2op, 2op+1), ALL 4 z in registers.
// y loaded once per (k,i) as float4 and reused across the 4 z slices.
// grid = sum_l (2l+1)*ceil((2l+1)/8) = 800
#define K4_GRID 800
__global__ __launch_bounds__(256) void k_so3mm() {
    int b = blockIdx.x;
    int l = 0, m = 0, ch = 0;
    {
        int off = 0;
        for (int ll = 15; ll >= 0; --ll) {
            int n1 = 2 * ll + 1, nch = (n1 + 7) >> 3;
            int cnt = n1 * nch;
            if (b < off + cnt) { l = ll; int r = b - off; m = r / nch; ch = r % nch; break; }
            off += cnt;
        }
    }
    int n1 = 2 * l + 1;
    int base = baseL(l);
    __shared__ float2 sx[31 * ZI];
    int tid = threadIdx.x;
    // cooperative load of x rows for (l, m, k=0..n1-1): contiguous, float4
    {
        const float4* xsrc = reinterpret_cast<const float4*>(g_xh + (size_t)(base + m * n1) * ZI);
        float4* xdst = reinterpret_cast<float4*>(sx);
        for (int idx = tid; idx < n1 * (ZI / 2); idx += 256) xdst[idx] = xsrc[idx];
    }
    __syncthreads();

    int op  = tid & 31;          // o pair: o = 2*op, 2*op+1
    int npp = tid >> 5;          // 0..7
    int np  = ch * 8 + npp;
    bool valid = np < n1;
    int npc = valid ? np : n1 - 1;

    // acc[z][oi] complex
    float2 acc[4][2];
    #pragma unroll
    for (int z = 0; z < 4; z++) {
        acc[z][0] = make_float2(0.f, 0.f);
        acc[z][1] = make_float2(0.f, 0.f);
    }

    for (int k = 0; k < n1; k++) {
        const float4* row = reinterpret_cast<const float4*>(
            g_yh + ((size_t)(base + k * n1 + npc)) * 2048);
        const float2* xk = sx + k * ZI;
        #pragma unroll 4
        for (int i = 0; i < FIN; i++) {
            float4 y = __ldg(&row[i * 32 + op]);
            #pragma unroll
            for (int z = 0; z < 4; z++) {
                float2 a = xk[z * FIN + i];
                acc[z][0].x += a.x * y.x - a.y * y.y;
                acc[z][0].y += a.x * y.y + a.y * y.x;
                acc[z][1].x += a.x * y.z - a.y * y.w;
                acc[z][1].y += a.x * y.w + a.y * y.z;
            }
        }
    }
    if (valid) {
        int idx = base + m * n1 + np;
        int o0 = 2 * op;
        #pragma unroll
        for (int z = 0; z < 4; z++) {
            g_zh[(size_t)(z * 64 + o0)     * L_TOT + idx] = acc[z][0];
            g_zh[(size_t)(z * 64 + o0 + 1) * L_TOT + idx] = acc[z][1];
        }
    }
}

// ---------------- K5: fused scatter (wigner_inv * zh -> bins) + inverse FFT2 + real + bias ----------------
__global__ __launch_bounds__(1024) void k_inv(const float* __restrict__ wig,
                                              const float* __restrict__ bias,
                                              float* __restrict__ out) {
    __shared__ float2 plane[32][33];
    __shared__ float2 U[32][33];
    __shared__ float2 W[32];
    int blk = blockIdx.x;           // z*2048 + o*32 + b
    int bb = blk & 31;
    int o  = (blk >> 5) & 63;
    int z  = blk >> 11;
    int tid = threadIdx.x;
    int r = tid >> 5, c = tid & 31;
    if (tid < 32) {
        float s, co;
        sincosf(6.283185307179586f * (float)tid / 32.0f, &s, &co);  // inverse: e^{+i...}
        W[tid] = make_float2(co, s);
    }
    plane[r][c] = make_float2(0.f, 0.f);
    __syncthreads();
    if (tid < 961) {
        int m = tid / 31 - 15, n = tid % 31 - 15;
        int am = m < 0 ? -m : m, an = n < 0 ? -n : n;
        int lmin = am > an ? am : an;
        float2 acc = make_float2(0.f, 0.f);
        const float2* zrow = g_zh + (size_t)(z * 64 + o) * L_TOT;
        const float*  wp   = wig + (size_t)bb * L_TOT;
        for (int l = lmin; l < 16; ++l) {
            int idx = baseL(l) + (m + l) * (2 * l + 1) + (n + l);
            float w = __ldg(&wp[idx]);
            float2 v = zrow[idx];
            acc.x += w * v.x; acc.y += w * v.y;
        }
        plane[m & 31][n & 31] = acc;
    }
    __syncthreads();
    float2 u = make_float2(0.f, 0.f);
    #pragma unroll
    for (int mm = 0; mm < 32; mm++) {
        float2 p = plane[mm][c];
        float2 w = W[(mm * r) & 31];
        u.x += p.x * w.x - p.y * w.y;
        u.y += p.x * w.y + p.y * w.x;
    }
    U[r][c] = u;
    __syncthreads();
    float acc = 0.f;
    #pragma unroll
    for (int nn = 0; nn < 32; nn++) {
        float2 t = U[r][nn];
        float2 w = W[(nn * c) & 31];
        acc += t.x * w.x - t.y * w.y;
    }
    out[(size_t)blk * 1024 + tid] = acc * (1.0f / 1024.0f) + __ldg(&bias[o]);
}

// ---------------- launch ----------------
extern "C" void kernel_launch(void* const* d_in, const int* in_sizes, int n_in,
                              void* d_out, int out_size) {
    const float* x    = (const float*)d_in[0];
    const float* kern = (const float*)d_in[1];
    const float* bias = (const float*)d_in[2];
    const float* wf   = (const float*)d_in[3];
    const float* wi   = (const float*)d_in[4];
    const float* D_re = (const float*)d_in[5];
    const float* D_im = (const float*)d_in[6];
    float* out = (float*)d_out;

    k_fft_fwd<<<BATCH * FIN * NB, 1024>>>(x);
    k_fwd_contract<<<L_TOT, ZI>>>(wf);
    k_kernel_ft<<<dim3(L_TOT, 2), 1024>>>(D_re, D_im, kern);
    k_so3mm<<<K4_GRID, 256>>>();
    k_inv<<<BATCH * FOUT * NB, 1024>>>(wi, bias, out);
}

// round 5
// speedup vs baseline: 2.5963x; 1.4848x over previous
#include <cuda_runtime.h>
#include <cuda_bf16.h>
#include <math.h>

#define L_TOT 5456
#define NB    32
#define FIN   32
#define FOUT  64
#define BATCH 4
#define NGRID 12
#define ZI    128   // BATCH*FIN
#define ZO    256   // BATCH*FOUT

// -------- scratch (device globals; no runtime allocation) --------
// Xf layout: [b*1024 + mi*32 + ni][zi]  (zi innermost -> coalesced in K2)
__device__ float2 g_Xf[(size_t)NB * 1024 * ZI];                    // 33.5 MB
__device__ float2 g_xh[(size_t)L_TOT * ZI];                        // 5.6 MB
__device__ float2 g_yh[(size_t)L_TOT * FIN * FOUT];                // 89 MB (L2-resident)
__device__ float2 g_zh[(size_t)ZO * L_TOT];                        // 11.2 MB, layout [zo][lmn]

__device__ __forceinline__ int baseL(int l) {
    // sum_{l'<l} (2l'+1)^2 = l(2l-1)(2l+1)/3
    return l * (2 * l - 1) * (2 * l + 1) / 3;
}

// ---- in-warp 32-point radix-2 DIF FFT via shuffles.
// Input: lane i holds x[i] (natural order). Output: lane i holds X[bitrev5(i)].
// Wt[k] must hold e^{sign*i*2*pi*k/32} (sign=-1 forward, +1 inverse).
__device__ __forceinline__ void warp_fft32(float& re, float& im, const float2* __restrict__ Wt) {
    int lane = threadIdx.x & 31;
    #pragma unroll
    for (int h = 16; h >= 1; h >>= 1) {
        float vr = __shfl_xor_sync(0xffffffffu, re, h);
        float vi = __shfl_xor_sync(0xffffffffu, im, h);
        int k = (lane & (h - 1)) * (16 / h);
        float2 w = Wt[k];
        if ((lane & h) == 0) {
            re += vr; im += vi;
        } else {
            float tr = vr - re, ti = vi - im;
            re = tr * w.x - ti * w.y;
            im = tr * w.y + ti * w.x;
        }
    }
}

__device__ __forceinline__ int brev5(int lane) { return (int)(__brev((unsigned)lane) >> 27); }

// ---------------- K1: forward FFT2 of x, writes transposed Xf ----------------
__global__ __launch_bounds__(1024) void k_fft_fwd(const float* __restrict__ x) {
    __shared__ float2 S[32][33];
    __shared__ float2 Wt[16];
    int plane = blockIdx.x;                 // = zi*32 + b
    int zi = plane >> 5, b = plane & 31;
    int tid = threadIdx.x;
    int w = tid >> 5, lane = tid & 31;
    if (tid < 16) {
        float s, c;
        sincosf(-6.283185307179586f * (float)tid / 32.0f, &s, &c);
        Wt[tid] = make_float2(c, s);
    }
    float re = x[(size_t)plane * 1024 + tid];   // row a=w, col g=lane
    float im = 0.f;
    __syncthreads();
    // FFT over gamma (within row a=w)
    warp_fft32(re, im, Wt);
    S[w][brev5(lane)] = make_float2(re, im);    // store at natural ng
    __syncthreads();
    // FFT over alpha (column ng=w); lane runs over a
    float2 v = S[lane][w];
    re = v.x; im = v.y;
    warp_fft32(re, im, Wt);
    int ma = brev5(lane);
    g_Xf[((size_t)(b * 1024 + ma * 32 + w)) * ZI + zi] = make_float2(re, im);
}

// ---------------- K2: xh[lmn][zi] = sum_b wf[b,lmn] * Xf[b,m&31,n&31][zi] ----------------
__global__ __launch_bounds__(128) void k_fwd_contract(const float* __restrict__ wf) {
    int lmn = blockIdx.x;
    int l = 0;
    while (l < 15 && lmn >= baseL(l + 1)) ++l;
    int n1 = 2 * l + 1;
    int rem = lmn - baseL(l);
    int m = rem / n1 - l, n = rem % n1 - l;
    int mi = m & 31, ni = n & 31;
    __shared__ float sw[32];
    int t = threadIdx.x;  // zi
    if (t < 32) sw[t] = __ldg(&wf[t * L_TOT + lmn]);
    __syncthreads();
    const float2* xp = g_Xf + ((size_t)(mi * 32 + ni)) * ZI + t;
    float2 acc = make_float2(0.f, 0.f);
    #pragma unroll 8
    for (int b = 0; b < 32; b++) {
        float w = sw[b];
        float2 v = xp[(size_t)b * 1024 * ZI];
        acc.x += w * v.x; acc.y += w * v.y;
    }
    g_xh[(size_t)lmn * ZI + t] = acc;
}

// ---------------- K3: yh[lmn][q] = sum_j D[lmn,j] * kernel[q,j]  (tiled) ----------------
#define K3_LT 64
__global__ __launch_bounds__(256) void k_kernel_ft(const float* __restrict__ D_re,
                                                   const float* __restrict__ D_im,
                                                   const float* __restrict__ kern) {
    __shared__ float2 sD[K3_LT][NGRID];
    __shared__ float  sk[256 * 13];
    int lmn0 = blockIdx.x * K3_LT;
    int q0   = blockIdx.y * 256;
    int tid  = threadIdx.x;
    for (int idx = tid; idx < K3_LT * NGRID; idx += 256) {
        int ll = idx / NGRID, j = idx % NGRID;
        int lmn = lmn0 + ll;
        float dr = 0.f, di = 0.f;
        if (lmn < L_TOT) { dr = D_re[lmn * NGRID + j]; di = D_im[lmn * NGRID + j]; }
        sD[ll][j] = make_float2(dr, di);
    }
    for (int idx = tid; idx < 256 * NGRID; idx += 256) {
        int qq = idx / NGRID, j = idx % NGRID;
        sk[qq * 13 + j] = kern[(size_t)(q0 + qq) * NGRID + j];
    }
    __syncthreads();
    float kreg[NGRID];
    #pragma unroll
    for (int j = 0; j < NGRID; j++) kreg[j] = sk[tid * 13 + j];
    int q = q0 + tid;
    #pragma unroll 4
    for (int ll = 0; ll < K3_LT; ll++) {
        int lmn = lmn0 + ll;
        if (lmn >= L_TOT) break;
        float2 acc = make_float2(0.f, 0.f);
        #pragma unroll
        for (int j = 0; j < NGRID; j++) {
            float2 d = sD[ll][j];
            acc.x += kreg[j] * d.x;
            acc.y += kreg[j] * d.y;
        }
        g_yh[(size_t)lmn * 2048 + q] = acc;
    }
}

// ---------------- K4: per-l block matmul  zh = x^l @ y^l  (persistent) ----------------
// tile = (l desc, m, chunk of 8 np). 256 threads = npp(8) x op(32).
// Each thread: 1 np, o-pair (2op, 2op+1), ALL 4 z in registers.
// tiles = sum_l (2l+1)*ceil((2l+1)/8) = 800
#define K4_TILES  800
#define K4_BLOCKS 592
__global__ __launch_bounds__(256, 4) void k_so3mm() {
    __shared__ float2 sx[31 * ZI];
    int tid = threadIdx.x;
    for (int t = blockIdx.x; t < K4_TILES; t += K4_BLOCKS) {
        int l = 0, m = 0, ch = 0;
        {
            int off = 0;
            for (int ll = 15; ll >= 0; --ll) {
                int n1 = 2 * ll + 1, nch = (n1 + 7) >> 3;
                int cnt = n1 * nch;
                if (t < off + cnt) { l = ll; int r = t - off; m = r / nch; ch = r % nch; break; }
                off += cnt;
            }
        }
        int n1 = 2 * l + 1;
        int base = baseL(l);
        __syncthreads();   // protect sx reuse across persistent iterations
        {
            const float4* xsrc = reinterpret_cast<const float4*>(g_xh + (size_t)(base + m * n1) * ZI);
            float4* xdst = reinterpret_cast<float4*>(sx);
            for (int idx = tid; idx < n1 * (ZI / 2); idx += 256) xdst[idx] = xsrc[idx];
        }
        __syncthreads();

        int op  = tid & 31;          // o pair: o = 2*op, 2*op+1
        int npp = tid >> 5;          // 0..7
        int np  = ch * 8 + npp;
        bool valid = np < n1;
        int npc = valid ? np : n1 - 1;

        float2 acc[4][2];
        #pragma unroll
        for (int z = 0; z < 4; z++) {
            acc[z][0] = make_float2(0.f, 0.f);
            acc[z][1] = make_float2(0.f, 0.f);
        }

        for (int k = 0; k < n1; k++) {
            const float4* row = reinterpret_cast<const float4*>(
                g_yh + ((size_t)(base + k * n1 + npc)) * 2048);
            const float2* xk = sx + k * ZI;
            #pragma unroll 4
            for (int i = 0; i < FIN; i++) {
                float4 y = __ldg(&row[i * 32 + op]);
                #pragma unroll
                for (int z = 0; z < 4; z++) {
                    float2 a = xk[z * FIN + i];
                    acc[z][0].x += a.x * y.x - a.y * y.y;
                    acc[z][0].y += a.x * y.y + a.y * y.x;
                    acc[z][1].x += a.x * y.z - a.y * y.w;
                    acc[z][1].y += a.x * y.w + a.y * y.z;
                }
            }
        }
        if (valid) {
            int idx = base + m * n1 + np;
            int o0 = 2 * op;
            #pragma unroll
            for (int z = 0; z < 4; z++) {
                g_zh[(size_t)(z * 64 + o0)     * L_TOT + idx] = acc[z][0];
                g_zh[(size_t)(z * 64 + o0 + 1) * L_TOT + idx] = acc[z][1];
            }
        }
    }
}

// ---------------- K5: fused scatter (wigner_inv * zh -> bins) + inverse FFT2 + real + bias ----------------
__global__ __launch_bounds__(1024) void k_inv(const float* __restrict__ wig,
                                              const float* __restrict__ bias,
                                              float* __restrict__ out) {
    __shared__ float2 P[32][33];
    __shared__ float  U[32][33];
    __shared__ float2 Wt[16];
    int blk = blockIdx.x;           // z*2048 + o*32 + b
    int bb = blk & 31;
    int o  = (blk >> 5) & 63;
    int z  = blk >> 11;
    int tid = threadIdx.x;
    int w = tid >> 5, lane = tid & 31;
    if (tid < 16) {
        float s, c;
        sincosf(6.283185307179586f * (float)tid / 32.0f, &s, &c);  // inverse: e^{+i...}
        Wt[tid] = make_float2(c, s);
    }
    P[w][lane] = make_float2(0.f, 0.f);
    __syncthreads();
    // bin accumulation: one thread per (m,n) in [-15,15]^2
    if (tid < 961) {
        int m = tid / 31 - 15, n = tid % 31 - 15;
        int am = m < 0 ? -m : m, an = n < 0 ? -n : n;
        int lmin = am > an ? am : an;
        float2 acc = make_float2(0.f, 0.f);
        const float2* zrow = g_zh + (size_t)(z * 64 + o) * L_TOT;
        const float*  wp   = wig + (size_t)bb * L_TOT;
        for (int l = lmin; l < 16; ++l) {
            int idx = baseL(l) + (m + l) * (2 * l + 1) + (n + l);
            float ww = __ldg(&wp[idx]);
            float2 v = zrow[idx];
            acc.x += ww * v.x; acc.y += ww * v.y;
        }
        P[m & 31][n & 31] = acc;
    }
    __syncthreads();
    // inverse FFT over n (gamma): warp w = row mi; in-place (warp touches only its row)
    {
        float2 v = P[w][lane];
        float re = v.x, im = v.y;
        warp_fft32(re, im, Wt);
        P[w][brev5(lane)] = make_float2(re, im);
    }
    __syncthreads();
    // inverse FFT over m (alpha): warp w = column g=w; lane runs over m
    {
        float2 v = P[lane][w];
        float re = v.x, im = v.y;
        warp_fft32(re, im, Wt);
        U[brev5(lane)][w] = re * (1.0f / 1024.0f);   // real part only
    }
    __syncthreads();
    out[(size_t)blk * 1024 + tid] = U[w][lane] + __ldg(&bias[o]);
}

// ---------------- launch ----------------
extern "C" void kernel_launch(void* const* d_in, const int* in_sizes, int n_in,
                              void* d_out, int out_size) {
    const float* x    = (const float*)d_in[0];
    const float* kern = (const float*)d_in[1];
    const float* bias = (const float*)d_in[2];
    const float* wf   = (const float*)d_in[3];
    const float* wi   = (const float*)d_in[4];
    const float* D_re = (const float*)d_in[5];
    const float* D_im = (const float*)d_in[6];
    float* out = (float*)d_out;

    k_fft_fwd<<<BATCH * FIN * NB, 1024>>>(x);
    k_fwd_contract<<<L_TOT, ZI>>>(wf);
    k_kernel_ft<<<dim3((L_TOT + K3_LT - 1) / K3_LT, 8), 256>>>(D_re, D_im, kern);
    k_so3mm<<<K4_BLOCKS, 256>>>();
    k_inv<<<BATCH * FOUT * NB, 1024>>>(wi, bias, out);
}

// round 6
// speedup vs baseline: 2.9845x; 1.1495x over previous
#include <cuda_runtime.h>
#include <cuda_bf16.h>
#include <math.h>

#define L_TOT 5456
#define NB    32
#define FIN   32
#define FOUT  64
#define BATCH 4
#define NGRID 12
#define ZI    128   // BATCH*FIN
#define ZO    256   // BATCH*FOUT

typedef unsigned long long ull;

// -------- scratch (device globals; no runtime allocation) --------
// Xf layout: [b*1024 + mi*32 + ni][zi]  (zi innermost -> coalesced in K2)
__device__ float2 g_Xf[(size_t)NB * 1024 * ZI];                    // 33.5 MB
__device__ float2 g_xh[(size_t)L_TOT * ZI];                        // 5.6 MB
__device__ float2 g_yh[(size_t)L_TOT * FIN * FOUT];                // 89 MB (L2-resident)
__device__ float2 g_zh[(size_t)ZO * L_TOT];                        // 11.2 MB, layout [zo][lmn]

__device__ __forceinline__ int baseL(int l) {
    // sum_{l'<l} (2l'+1)^2 = l(2l-1)(2l+1)/3
    return l * (2 * l - 1) * (2 * l + 1) / 3;
}

// ---- packed f32x2 helpers (Blackwell FFMA2 path) ----
__device__ __forceinline__ ull pk2(unsigned lo, unsigned hi) {
    ull r;
    asm("mov.b64 %0, {%1, %2};" : "=l"(r) : "r"(lo), "r"(hi));
    return r;
}
__device__ __forceinline__ void fma2(ull& d, ull a, ull b) {
    asm("fma.rn.f32x2 %0, %1, %2, %0;" : "+l"(d) : "l"(a), "l"(b));
}

// ---- in-warp 32-point radix-2 DIF FFT via shuffles.
// Input: lane i holds x[i] (natural order). Output: lane i holds X[bitrev5(i)].
// Wt[k] must hold e^{sign*i*2*pi*k/32} (sign=-1 forward, +1 inverse).
__device__ __forceinline__ void warp_fft32(float& re, float& im, const float2* __restrict__ Wt) {
    int lane = threadIdx.x & 31;
    #pragma unroll
    for (int h = 16; h >= 1; h >>= 1) {
        float vr = __shfl_xor_sync(0xffffffffu, re, h);
        float vi = __shfl_xor_sync(0xffffffffu, im, h);
        int k = (lane & (h - 1)) * (16 / h);
        float2 w = Wt[k];
        if ((lane & h) == 0) {
            re += vr; im += vi;
        } else {
            float tr = vr - re, ti = vi - im;
            re = tr * w.x - ti * w.y;
            im = tr * w.y + ti * w.x;
        }
    }
}

__device__ __forceinline__ int brev5(int lane) { return (int)(__brev((unsigned)lane) >> 27); }

// ---------------- K1: forward FFT2 of x, writes transposed Xf ----------------
__global__ __launch_bounds__(1024) void k_fft_fwd(const float* __restrict__ x) {
    __shared__ float2 S[32][33];
    __shared__ float2 Wt[16];
    int plane = blockIdx.x;                 // = zi*32 + b
    int zi = plane >> 5, b = plane & 31;
    int tid = threadIdx.x;
    int w = tid >> 5, lane = tid & 31;
    if (tid < 16) {
        float s, c;
        sincosf(-6.283185307179586f * (float)tid / 32.0f, &s, &c);
        Wt[tid] = make_float2(c, s);
    }
    float re = x[(size_t)plane * 1024 + tid];   // row a=w, col g=lane
    float im = 0.f;
    __syncthreads();
    warp_fft32(re, im, Wt);
    S[w][brev5(lane)] = make_float2(re, im);
    __syncthreads();
    float2 v = S[lane][w];
    re = v.x; im = v.y;
    warp_fft32(re, im, Wt);
    int ma = brev5(lane);
    g_Xf[((size_t)(b * 1024 + ma * 32 + w)) * ZI + zi] = make_float2(re, im);
}

// ---------------- K2: xh[lmn][zi] = sum_b wf[b,lmn] * Xf[b,m&31,n&31][zi] ----------------
__global__ __launch_bounds__(128) void k_fwd_contract(const float* __restrict__ wf) {
    int lmn = blockIdx.x;
    int l = 0;
    while (l < 15 && lmn >= baseL(l + 1)) ++l;
    int n1 = 2 * l + 1;
    int rem = lmn - baseL(l);
    int m = rem / n1 - l, n = rem % n1 - l;
    int mi = m & 31, ni = n & 31;
    __shared__ float sw[32];
    int t = threadIdx.x;  // zi
    if (t < 32) sw[t] = __ldg(&wf[t * L_TOT + lmn]);
    __syncthreads();
    const float2* xp = g_Xf + ((size_t)(mi * 32 + ni)) * ZI + t;
    float2 acc = make_float2(0.f, 0.f);
    #pragma unroll 8
    for (int b = 0; b < 32; b++) {
        float w = sw[b];
        float2 v = xp[(size_t)b * 1024 * ZI];
        acc.x += w * v.x; acc.y += w * v.y;
    }
    g_xh[(size_t)lmn * ZI + t] = acc;
}

// ---------------- K3: yh[lmn][q] = sum_j D[lmn,j] * kernel[q,j]  (tiled) ----------------
#define K3_LT 64
__global__ __launch_bounds__(256) void k_kernel_ft(const float* __restrict__ D_re,
                                                   const float* __restrict__ D_im,
                                                   const float* __restrict__ kern) {
    __shared__ float2 sD[K3_LT][NGRID];
    __shared__ float  sk[256 * 13];
    int lmn0 = blockIdx.x * K3_LT;
    int q0   = blockIdx.y * 256;
    int tid  = threadIdx.x;
    for (int idx = tid; idx < K3_LT * NGRID; idx += 256) {
        int ll = idx / NGRID, j = idx % NGRID;
        int lmn = lmn0 + ll;
        float dr = 0.f, di = 0.f;
        if (lmn < L_TOT) { dr = D_re[lmn * NGRID + j]; di = D_im[lmn * NGRID + j]; }
        sD[ll][j] = make_float2(dr, di);
    }
    for (int idx = tid; idx < 256 * NGRID; idx += 256) {
        int qq = idx / NGRID, j = idx % NGRID;
        sk[qq * 13 + j] = kern[(size_t)(q0 + qq) * NGRID + j];
    }
    __syncthreads();
    float kreg[NGRID];
    #pragma unroll
    for (int j = 0; j < NGRID; j++) kreg[j] = sk[tid * 13 + j];
    int q = q0 + tid;
    #pragma unroll 4
    for (int ll = 0; ll < K3_LT; ll++) {
        int lmn = lmn0 + ll;
        if (lmn >= L_TOT) break;
        float2 acc = make_float2(0.f, 0.f);
        #pragma unroll
        for (int j = 0; j < NGRID; j++) {
            float2 d = sD[ll][j];
            acc.x += kreg[j] * d.x;
            acc.y += kreg[j] * d.y;
        }
        g_yh[(size_t)lmn * 2048 + q] = acc;
    }
}

// ---------------- K4: per-l block matmul  zh = x^l @ y^l  (FFMA2 path) ----------------
// tile = (l desc, m, chunk of 8 np). 256 threads = npp(8) x op(32).
// Each thread: 1 np, o-pair (2op, 2op+1), ALL 4 z in registers (packed f32x2 acc).
// x pre-duplicated in smem as (ax, ax, -ay, ay); y loaded once per (k,i) as LDG.128.
// tiles = sum_l (2l+1)*ceil((2l+1)/8) = 800
#define K4_GRID 800
#define K4_KC   16
__global__ __launch_bounds__(256) void k_so3mm() {
    int b = blockIdx.x;
    int l = 0, m = 0, ch = 0;
    {
        int off = 0;
        for (int ll = 15; ll >= 0; --ll) {
            int n1 = 2 * ll + 1, nch = (n1 + 7) >> 3;
            int cnt = n1 * nch;
            if (b < off + cnt) { l = ll; int r = b - off; m = r / nch; ch = r % nch; break; }
            off += cnt;
        }
    }
    int n1 = 2 * l + 1;
    int base = baseL(l);
    __shared__ uint4 sx[K4_KC][ZI];   // (ax, ax, -ay, ay) as bit patterns; 32 KB
    int tid = threadIdx.x;

    int op  = tid & 31;          // o pair: o = 2*op, 2*op+1
    int npp = tid >> 5;          // 0..7
    int np  = ch * 8 + npp;
    bool valid = np < n1;
    int npc = valid ? np : n1 - 1;

    ull acc[4][2];
    #pragma unroll
    for (int z = 0; z < 4; z++) { acc[z][0] = 0ull; acc[z][1] = 0ull; }

    for (int kc = 0; kc < n1; kc += K4_KC) {
        int kend = kc + K4_KC < n1 ? kc + K4_KC : n1;
        int cnt = (kend - kc) * ZI;
        __syncthreads();
        for (int idx = tid; idx < cnt; idx += 256) {
            int kk = idx >> 7, zi = idx & 127;
            float2 a = g_xh[(size_t)(base + m * n1 + kc + kk) * ZI + zi];
            float nay = -a.y;
            sx[kk][zi] = make_uint4(__float_as_uint(a.x), __float_as_uint(a.x),
                                    __float_as_uint(nay), __float_as_uint(a.y));
        }
        __syncthreads();

        for (int k = kc; k < kend; k++) {
            const uint4* row = reinterpret_cast<const uint4*>(
                g_yh + ((size_t)(base + k * n1 + npc)) * 2048);
            const uint4* xk = sx[k - kc];
            #pragma unroll 4
            for (int i = 0; i < FIN; i++) {
                uint4 y = __ldg(&row[i * 32 + op]);
                ull y01 = pk2(y.x, y.y);
                ull y10 = pk2(y.y, y.x);
                ull y23 = pk2(y.z, y.w);
                ull y32 = pk2(y.w, y.z);
                #pragma unroll
                for (int z = 0; z < 4; z++) {
                    uint4 xq = xk[z * FIN + i];
                    ull axax  = pk2(xq.x, xq.y);
                    ull nayay = pk2(xq.z, xq.w);
                    fma2(acc[z][0], axax,  y01);
                    fma2(acc[z][0], nayay, y10);
                    fma2(acc[z][1], axax,  y23);
                    fma2(acc[z][1], nayay, y32);
                }
            }
        }
    }
    if (valid) {
        int idx = base + m * n1 + np;
        int o0 = 2 * op;
        #pragma unroll
        for (int z = 0; z < 4; z++) {
            float2 r0 = make_float2(__uint_as_float((unsigned)(acc[z][0] & 0xffffffffull)),
                                    __uint_as_float((unsigned)(acc[z][0] >> 32)));
            float2 r1 = make_float2(__uint_as_float((unsigned)(acc[z][1] & 0xffffffffull)),
                                    __uint_as_float((unsigned)(acc[z][1] >> 32)));
            g_zh[(size_t)(z * 64 + o0)     * L_TOT + idx] = r0;
            g_zh[(size_t)(z * 64 + o0 + 1) * L_TOT + idx] = r1;
        }
    }
}

// ---------------- K5: fused scatter (wigner_inv * zh -> bins) + inverse FFT2 + real + bias ----------------
__global__ __launch_bounds__(1024) void k_inv(const float* __restrict__ wig,
                                              const float* __restrict__ bias,
                                              float* __restrict__ out) {
    __shared__ float2 P[32][33];
    __shared__ float  U[32][33];
    __shared__ float2 Wt[16];
    int blk = blockIdx.x;           // z*2048 + o*32 + b
    int bb = blk & 31;
    int o  = (blk >> 5) & 63;
    int z  = blk >> 11;
    int tid = threadIdx.x;
    int w = tid >> 5, lane = tid & 31;
    if (tid < 16) {
        float s, c;
        sincosf(6.283185307179586f * (float)tid / 32.0f, &s, &c);  // inverse: e^{+i...}
        Wt[tid] = make_float2(c, s);
    }
    P[w][lane] = make_float2(0.f, 0.f);
    __syncthreads();
    if (tid < 961) {
        int m = tid / 31 - 15, n = tid % 31 - 15;
        int am = m < 0 ? -m : m, an = n < 0 ? -n : n;
        int lmin = am > an ? am : an;
        float2 acc = make_float2(0.f, 0.f);
        const float2* zrow = g_zh + (size_t)(z * 64 + o) * L_TOT;
        const float*  wp   = wig + (size_t)bb * L_TOT;
        for (int l = lmin; l < 16; ++l) {
            int idx = baseL(l) + (m + l) * (2 * l + 1) + (n + l);
            float ww = __ldg(&wp[idx]);
            float2 v = zrow[idx];
            acc.x += ww * v.x; acc.y += ww * v.y;
        }
        P[m & 31][n & 31] = acc;
    }
    __syncthreads();
    {
        float2 v = P[w][lane];
        float re = v.x, im = v.y;
        warp_fft32(re, im, Wt);
        P[w][brev5(lane)] = make_float2(re, im);
    }
    __syncthreads();
    {
        float2 v = P[lane][w];
        float re = v.x, im = v.y;
        warp_fft32(re, im, Wt);
        U[brev5(lane)][w] = re * (1.0f / 1024.0f);   // real part only
    }
    __syncthreads();
    out[(size_t)blk * 1024 + tid] = U[w][lane] + __ldg(&bias[o]);
}

// ---------------- launch ----------------
extern "C" void kernel_launch(void* const* d_in, const int* in_sizes, int n_in,
                              void* d_out, int out_size) {
    const float* x    = (const float*)d_in[0];
    const float* kern = (const float*)d_in[1];
    const float* bias = (const float*)d_in[2];
    const float* wf   = (const float*)d_in[3];
    const float* wi   = (const float*)d_in[4];
    const float* D_re = (const float*)d_in[5];
    const float* D_im = (const float*)d_in[6];
    float* out = (float*)d_out;

    k_fft_fwd<<<BATCH * FIN * NB, 1024>>>(x);
    k_fwd_contract<<<L_TOT, ZI>>>(wf);
    k_kernel_ft<<<dim3((L_TOT + K3_LT - 1) / K3_LT, 8), 256>>>(D_re, D_im, kern);
    k_so3mm<<<K4_GRID, 256>>>();
    k_inv<<<BATCH * FOUT * NB, 1024>>>(wi, bias, out);
}